// round 17
// baseline (speedup 1.0000x reference)
#include <cuda_runtime.h>
#include <cuda_fp16.h>
#include <cstdint>

#define NC 16
#define CS 32
#define NH 16
#define NF 512
#define BATCH 131072
#define MROWS 64
#define THREADS 256

#define AS_BYTES 1040                  // A row stride: 1040 % 128 = 16 -> ldmatrix conflict-free
#define SM_STG   (MROWS * AS_BYTES)    // staging buffer (16 rows fp32, natural order)
#define SM_TOTAL (SM_STG + 16 * NF * 4)   // 66560 + 32768 = 99328 -> 2 CTAs/SM

__device__ float    g_bias[NC * CS];
__device__ int      g_pos[NF];            // pos[feature] = cl*32 + k
// Fragment-order W table: idx = ((((cl*4+t)*2+s)*2+hl)*2+reg)*32+lane.
__device__ uint32_t g_Wfrag[NC * 4 * 2 * 2 * 2 * 32];

// Single fused prep: computes g_Wfrag directly (each entry = 2 fused dots),
// plus bias and the inverse permutation.
__global__ void prep_kernel(const float* __restrict__ enc_w,
                            const float* __restrict__ enc_b,
                            const float* __restrict__ dec_w,
                            const float* __restrict__ dec_b,
                            const int*   __restrict__ clusters) {
    int i = blockIdx.x * blockDim.x + threadIdx.x;
    if (i < NC * 4 * 2 * 2 * 2 * 32) {
        int lane = i & 31;
        int reg  = (i >> 5) & 1;
        int hl   = (i >> 6) & 1;
        int s    = (i >> 7) & 1;
        int t    = (i >> 8) & 3;
        int cl   = i >> 10;
        int c = t * 8 + (lane >> 2);
        int k = s * 16 + 2 * (lane & 3) + reg * 8;
        const float* dw = dec_w + (cl * CS + c) * NH;
        const float* ew = enc_w + cl * NH * CS;
        float w0 = 0.f, w1 = 0.f;
        for (int h = 0; h < NH; h++) {
            w0 += dw[h] * ew[h * CS + k];
            w1 += dw[h] * ew[h * CS + k + 1];
        }
        __half h0 = __float2half_rn(w0);
        __half h1 = __float2half_rn(w1);
        __half v0, v1;
        if (hl == 0) { v0 = h0; v1 = h1; }
        else {
            v0 = __float2half_rn(w0 - __half2float(h0));
            v1 = __float2half_rn(w1 - __half2float(h1));
        }
        g_Wfrag[i] = (uint32_t)__half_as_ushort(v0)
                   | ((uint32_t)__half_as_ushort(v1) << 16);
    }
    if (i < NC * CS) {
        int n = i >> 5;
        const float* dw = dec_w + i * NH;
        const float* eb = enc_b + n * NH;
        float s = dec_b[i];
        for (int h = 0; h < NH; h++) s += dw[h] * eb[h];
        g_bias[i] = s;
        g_pos[clusters[i]] = i;
    }
}

__device__ __forceinline__ void mma_16816(float* acc, const uint32_t* A,
                                          const uint32_t* B) {
    asm volatile("mma.sync.aligned.m16n8k16.row.col.f32.f16.f16.f32 "
                 "{%0,%1,%2,%3},{%4,%5,%6,%7},{%8,%9},{%0,%1,%2,%3};"
                 : "+f"(acc[0]), "+f"(acc[1]), "+f"(acc[2]), "+f"(acc[3])
                 : "r"(A[0]), "r"(A[1]), "r"(A[2]), "r"(A[3]),
                   "r"(B[0]), "r"(B[1]));
}
__device__ __forceinline__ void ldsm4(uint32_t* R, uint32_t addr) {
    asm volatile("ldmatrix.sync.aligned.m8n8.x4.shared.b16 {%0,%1,%2,%3},[%4];"
                 : "=r"(R[0]), "=r"(R[1]), "=r"(R[2]), "=r"(R[3]) : "r"(addr));
}
__device__ __forceinline__ void cp_async16(uint32_t smem, const void* g) {
    asm volatile("cp.async.cg.shared.global [%0], [%1], 16;"
                 :: "r"(smem), "l"(g) : "memory");
}

// 64-row tile, 2 CTAs/SM, split-phase pipeline:
//   cp.async rows 32-47 -> staging | LDG-scatter rows 0-31 | barrier
//   compute m0,m1 | wait+barrier
//   LDG rows 48-63 -> regs; convert-scatter staging (hides LDG latency);
//   scatter regs | barrier | compute m2,m3.
__global__ void __launch_bounds__(THREADS, 2)
ensemble_kernel(const float* __restrict__ x, float* __restrict__ y) {
    extern __shared__ __align__(16) char smem[];
    uint32_t sb;
    asm("{ .reg .u64 t0; cvta.to.shared.u64 t0, %1; cvt.u32.u64 %0, t0; }"
        : "=r"(sb) : "l"(smem));
    const int tid  = threadIdx.x;
    const int warp = tid >> 5;
    const int lane = tid & 31;
    const long long row0 = (long long)blockIdx.x * MROWS;

    // ---- stationary B fragments from g_Wfrag (coalesced, L2-hot) ----
    uint32_t bh[2][4][2][2], bl[2][4][2][2];
#pragma unroll
    for (int ci = 0; ci < 2; ci++) {
        int cl = warp * 2 + ci;
#pragma unroll
        for (int t = 0; t < 4; t++) {
#pragma unroll
            for (int s = 0; s < 2; s++) {
                int base = (((cl * 4 + t) * 2 + s) * 2) * 2 * 32 + lane;
                bh[ci][t][s][0] = g_Wfrag[base];
                bh[ci][t][s][1] = g_Wfrag[base + 32];
                bl[ci][t][s][0] = g_Wfrag[base + 64];
                bl[ci][t][s][1] = g_Wfrag[base + 96];
            }
        }
    }

    const int4* pv = (const int4*)g_pos;

    // ---- phase A: async-stage rows 32-47 (natural order) ----
    {
        const char* src = (const char*)(x + (row0 + 32) * NF);
        for (int i = 0; i < 8; i++) {
            int idx = tid + i * THREADS;          // 0..2047 16B chunks
            cp_async16(sb + SM_STG + idx * 16, src + idx * 16);
        }
        asm volatile("cp.async.commit_group;" ::: "memory");
    }

    // ---- phase B: LDG-scatter rows 0-31 ----
    {
        const float4* xv = (const float4*)x + row0 * (NF / 4);
        for (int i = 0; i < 16; i++) {
            int idx = tid + i * THREADS;          // f4 index, rows 0-31
            int r  = idx >> 7;
            int f4 = idx & 127;
            float4 v = xv[idx];
            int4   p = pv[f4];
            char* base = smem + r * AS_BYTES;
            *(__half*)(base + p.x * 2) = __float2half_rn(v.x);
            *(__half*)(base + p.y * 2) = __float2half_rn(v.y);
            *(__half*)(base + p.z * 2) = __float2half_rn(v.z);
            *(__half*)(base + p.w * 2) = __float2half_rn(v.w);
        }
    }
    __syncthreads();

    // A-frag lane address component
    const int arow = ((lane & 7) + ((lane >> 3) & 1) * 8) * AS_BYTES
                   + ((lane >> 4) & 1) * 16;

#pragma unroll 1
    for (int m = 0; m < 4; m++) {
        if (m == 2) {
            // ---- phase C: finish the second half of the tile ----
            asm volatile("cp.async.wait_group 0;" ::: "memory");
            __syncthreads();   // staging visible to all; m0/m1 ldsm complete

            // issue LDG for rows 48-63 (latency hidden by convert below)
            float4 v[8];
            const float4* xv2 = (const float4*)x + (row0 + 48) * (NF / 4);
#pragma unroll
            for (int i = 0; i < 8; i++) v[i] = xv2[tid + i * THREADS];

            // convert-scatter staging rows 32-47 (LDS -> STS, no DRAM dep)
            const float4* sv = (const float4*)(smem + SM_STG);
#pragma unroll
            for (int i = 0; i < 8; i++) {
                int idx = tid + i * THREADS;      // f4 index, rows 32-47
                int r  = 32 + (idx >> 7);
                int f4 = idx & 127;
                float4 w = sv[idx];
                int4   p = pv[f4];
                char* base = smem + r * AS_BYTES;
                *(__half*)(base + p.x * 2) = __float2half_rn(w.x);
                *(__half*)(base + p.y * 2) = __float2half_rn(w.y);
                *(__half*)(base + p.z * 2) = __float2half_rn(w.z);
                *(__half*)(base + p.w * 2) = __float2half_rn(w.w);
            }
            // scatter the register rows 48-63
#pragma unroll
            for (int i = 0; i < 8; i++) {
                int idx = tid + i * THREADS;
                int r  = 48 + (idx >> 7);
                int f4 = idx & 127;
                int4  p = pv[f4];
                char* base = smem + r * AS_BYTES;
                *(__half*)(base + p.x * 2) = __float2half_rn(v[i].x);
                *(__half*)(base + p.y * 2) = __float2half_rn(v[i].y);
                *(__half*)(base + p.z * 2) = __float2half_rn(v[i].z);
                *(__half*)(base + p.w * 2) = __float2half_rn(v[i].w);
            }
            __syncthreads();
        }

        float acc[2][4][4];
#pragma unroll
        for (int ci = 0; ci < 2; ci++) {
            uint32_t a[2][4];
#pragma unroll
            for (int s = 0; s < 2; s++) {
                int addr = m * 16 * AS_BYTES + (warp * 2 + ci) * 64 + s * 32 + arow;
                ldsm4(a[s], sb + addr);
            }
#pragma unroll
            for (int t = 0; t < 4; t++) {
                acc[ci][t][0] = 0.f; acc[ci][t][1] = 0.f;
                acc[ci][t][2] = 0.f; acc[ci][t][3] = 0.f;
                mma_16816(acc[ci][t], a[0], bh[ci][t][0]);
                mma_16816(acc[ci][t], a[1], bh[ci][t][1]);
                mma_16816(acc[ci][t], a[0], bl[ci][t][0]);
                mma_16816(acc[ci][t], a[1], bl[ci][t][1]);
            }
        }

        const long long rlo = row0 + m * 16 + (lane >> 2);
#pragma unroll
        for (int ci = 0; ci < 2; ci++) {
#pragma unroll
            for (int t = 0; t < 4; t++) {
                int col = warp * 64 + ci * 32 + t * 8 + 2 * (lane & 3);
                float2 bv = __ldg((const float2*)(g_bias + col));
                float2 o0, o1;
                o0.x = acc[ci][t][0] + bv.x;
                o0.y = acc[ci][t][1] + bv.y;
                o1.x = acc[ci][t][2] + bv.x;
                o1.y = acc[ci][t][3] + bv.y;
                *(float2*)(y + rlo * NF + col)       = o0;
                *(float2*)(y + (rlo + 8) * NF + col) = o1;
            }
        }
    }
}

extern "C" void kernel_launch(void* const* d_in, const int* in_sizes, int n_in,
                              void* d_out, int out_size) {
    const float* x        = (const float*)d_in[0];
    const int*   clusters = (const int*)  d_in[1];
    const float* enc_w    = (const float*)d_in[2];
    const float* enc_b    = (const float*)d_in[3];
    const float* dec_w    = (const float*)d_in[4];
    const float* dec_b    = (const float*)d_in[5];
    float*       y        = (float*)d_out;

    static int attr_set = 0;
    if (!attr_set) {
        cudaFuncSetAttribute(ensemble_kernel,
                             cudaFuncAttributeMaxDynamicSharedMemorySize, SM_TOTAL);
        attr_set = 1;
    }

    prep_kernel<<<32, 512>>>(enc_w, enc_b, dec_w, dec_b, clusters);
    ensemble_kernel<<<BATCH / MROWS, THREADS, SM_TOTAL>>>(x, y);
}